// round 17
// baseline (speedup 1.0000x reference)
#include <cuda_runtime.h>
#include <stdint.h>

// ---------------------------------------------------------------------------
// VanDerWallsSurface: scatter point features into a 128^3 voxel grid.
//  out[b,x,y,z] = [max f0, min f1, mean f2] over points whose sphere covers
//  the voxel (within the 5x5x5 neighborhood of round(coords)), else zeros.
//
// R16: graph-level batch pipelining (R11 kernels verbatim, split by batch).
//  Evidence: sweep floor ~27us (write ceiling, 5 store paths agree), scatter
//  ~10us; in-kernel fusion failed twice (R6 wave serialization, R14 drain
//  contention); scatter restructures failed twice (R10, R15).
//  R16: the 4 batches are fully independent (disjoint voxel/Acc/bitmap
//  ranges). Scatters run on a second stream; each batch's sweep waits on
//  that batch's scatter event. The captured graph has parallel branches:
//  scatter(i+1..) overlaps sweep(i) — latency-bound work hiding under
//  BW-bound work, interleaved by the CTA distributor (not wave-ordered).
//
//  - Order-preserving uint encodings make 0 the neutral element for all four
//    accumulators -> scratch is a zero-initialized static; the sweep re-zeroes
//    dirty Acc entries and its bitmap words: all-zero across graph replays.
// ---------------------------------------------------------------------------

#define VOL        128
#define NB         4
#define NPTS       4096
#define NPOINTS    (NB * NPTS)            // 16384
#define KOFF       125                    // 5x5x5 offsets
#define TOTAL_VOX  (NB * VOL * VOL * VOL) // 8,388,608
#define NLINES     (TOTAL_VOX / 8)        // 1,048,576 (8 Acc per 128B line)
#define NWORDS     (NLINES / 32)          // 32,768 bitmap words
#define TPB        256

#define NCAND_B       (NPTS * KOFF)       // 512,000 candidates per batch
#define SCAT_BLOCKS_B (NCAND_B / TPB)     // 2,000 blocks per batch
#define WPB           8                   // bitmap words per sweep block
#define WORDS_B       (NWORDS / NB)       // 8,192 words per batch
#define SWEEP_BLOCKS_B (WORDS_B / WPB)    // 1,024 blocks per batch

// Interleaved per-voxel accumulator: one 128B cache line covers all four
// fields of 8 z-adjacent voxels. All neutral elements are 0.
struct Acc {
    unsigned int maxk;  // max-key of f0
    unsigned int mink;  // ~min-key of f1 (min via max)
    unsigned int cnt;   // hit count
    float        sum;   // sum of f2
};
__device__ Acc          g_acc[TOTAL_VOX];  // zero-init; kept zero by k_sweep
__device__ unsigned int g_dirty[NWORDS];   // 1 bit per Acc line; cleared by k_sweep

// Order-preserving float -> uint key. For any finite non-NaN f, fkey(f) > 0,
// so 0 is a valid "empty" sentinel for atomicMax accumulation.
__device__ __forceinline__ unsigned int fkey(float f) {
    unsigned int u = __float_as_uint(f);
    return (u & 0x80000000u) ? ~u : (u | 0x80000000u);
}
__device__ __forceinline__ float funkey(unsigned int k) {
    unsigned int u = (k & 0x80000000u) ? (k ^ 0x80000000u) : ~k;
    return __uint_as_float(u);
}

// Kernel A (R11 body): one thread per (point, offset) candidate within ONE
// batch; hits do 4 atomics into the voxel's interleaved Acc plus one
// dirty-bit atomicOr per touched line.
__global__ void __launch_bounds__(TPB) k_scatter(
    const float4* __restrict__ cr,     // (B*N) x [cx, cy, cz, r]
    const float*  __restrict__ feat,   // (B*N) x 3
    int pbase)                         // first point of this batch
{
    int t  = blockIdx.x * TPB + threadIdx.x;   // candidate id within batch
    int k  = t % KOFF;
    int pn = pbase + t / KOFF;                 // global point id

    float4 c = __ldg(cr + pn);  // 125 consecutive threads share -> L1 broadcast

    int ox = k / 25 - 2;
    int oy = (k / 5) % 5 - 2;
    int oz = k % 5 - 2;

    // jnp.round == round-half-to-even == rn conversions
    int vx = __float2int_rn(c.x) + ox;
    int vy = __float2int_rn(c.y) + oy;
    int vz = __float2int_rn(c.z) + oz;

    // Exact IEEE ops, left-to-right sum, matching the reference (no FMA
    // contraction that could flip sphere-boundary membership).
    float dx = __fsub_rn((float)vx, c.x);
    float dy = __fsub_rn((float)vy, c.y);
    float dz = __fsub_rn((float)vz, c.z);
    float d2 = __fadd_rn(__fadd_rn(__fmul_rn(dx, dx), __fmul_rn(dy, dy)),
                         __fmul_rn(dz, dz));

    float rr = __fdiv_rn(rintf(__fmul_rn(c.w, 1000.0f)), 1000.0f);
    float r2 = __fmul_rn(rr, rr);

    bool ok = (d2 <= r2)
            && ((unsigned)vx < VOL) && ((unsigned)vy < VOL) && ((unsigned)vz < VOL);
    if (!ok) return;

    unsigned e = (unsigned)((pn >> 12) * (VOL * VOL * VOL)
                            + ((vx * VOL + vy) * VOL + vz));

    const float* fp = feat + (size_t)pn * 3;
    float f0 = __ldg(fp + 0);
    float f1 = __ldg(fp + 1);
    float f2 = __ldg(fp + 2);

    Acc* a = &g_acc[e];
    atomicMax(&a->maxk, fkey(f0));
    atomicMax(&a->mink, ~fkey(f1));     // min via max of complemented key
    atomicAdd(&a->cnt, 1u);
    atomicAdd(&a->sum, f2);

    unsigned line = e >> 3;             // 8 Acc per 128B line
    atomicOr(&g_dirty[line >> 5], 1u << (line & 31u));
}

// Kernel B (R11 body): block handles WPB=8 bitmap words (8 x 256 voxels) of
// ONE batch. Clean voxel -> 12B of zeros; dirty line -> 16B Acc read
// (L2-hot), decode, 12B out, 16B Acc clean. Plain write-back stores. After
// the loop, one barrier, then threads 0..7 clear their dirty words.
__global__ void __launch_bounds__(TPB) k_sweep(
    float* __restrict__ out,
    unsigned wbase)                    // first bitmap word of this batch
{
    unsigned b = blockIdx.x;
    unsigned dirtyflags = 0u;

#pragma unroll
    for (int it = 0; it < WPB; it++) {
        unsigned widx = wbase + b * WPB + it;
        unsigned w = g_dirty[widx];                // block-uniform broadcast
        dirtyflags |= (w != 0u ? 1u : 0u) << it;

        unsigned e = widx * 256 + threadIdx.x;     // voxel id
        size_t   o = (size_t)e * 3;                // 12B/thread, coalesced

        if (((w >> ((threadIdx.x >> 3) & 31u)) & 1u) == 0u) {  // clean line
            out[o + 0] = 0.0f;
            out[o + 1] = 0.0f;
            out[o + 2] = 0.0f;
        } else {
            uint4* ap = reinterpret_cast<uint4*>(g_acc) + e;   // lane-dense
            uint4 a = *ap;
            float v0 = 0.0f, v1 = 0.0f, v2 = 0.0f;
            if (a.z != 0u) {                       // cnt != 0
                v0 = funkey(a.x);
                v1 = funkey(~a.y);
                v2 = __fdiv_rn(__uint_as_float(a.w), (float)a.z);
                *ap = make_uint4(0u, 0u, 0u, 0u);  // self-clean for next call
            }
            out[o + 0] = v0;
            out[o + 1] = v1;
            out[o + 2] = v2;
        }
    }

    // All threads have consumed their words; clear the dirty ones.
    __syncthreads();
    if (threadIdx.x < WPB && ((dirtyflags >> threadIdx.x) & 1u))
        g_dirty[wbase + b * WPB + threadIdx.x] = 0u;
}

// Second stream + events, created at module load (before any graph capture;
// no device-memory allocation happens in kernel_launch itself).
static cudaStream_t g_aux;
static cudaEvent_t  g_evFork;
static cudaEvent_t  g_evB[NB];
namespace {
struct StreamInit {
    StreamInit() {
        cudaStreamCreateWithFlags(&g_aux, cudaStreamNonBlocking);
        cudaEventCreateWithFlags(&g_evFork, cudaEventDisableTiming);
        for (int i = 0; i < NB; i++)
            cudaEventCreateWithFlags(&g_evB[i], cudaEventDisableTiming);
    }
};
static StreamInit g_si;
}

extern "C" void kernel_launch(void* const* d_in, const int* in_sizes, int n_in,
                              void* d_out, int out_size)
{
    const float4* cr   = (const float4*)d_in[0];  // coordinates_radii (B,N,4)
    const float*  feat = (const float*)d_in[1];   // features (B,N,3)
    float*        out  = (float*)d_out;           // (B,128,128,128,3) f32

    // Fork: tie g_aux into the capture rooted on the default stream.
    cudaEventRecord(g_evFork, 0);
    cudaStreamWaitEvent(g_aux, g_evFork, 0);

    // All 4 batch scatters run back-to-back on the aux stream.
    for (int i = 0; i < NB; i++) {
        k_scatter<<<SCAT_BLOCKS_B, TPB, 0, g_aux>>>(cr, feat, i * NPTS);
        cudaEventRecord(g_evB[i], g_aux);
    }

    // Each batch's sweep (main stream) waits only on its own scatter, so
    // sweep(i) overlaps scatter(i+1..NB-1).
    for (int i = 0; i < NB; i++) {
        cudaStreamWaitEvent(0, g_evB[i], 0);
        k_sweep<<<SWEEP_BLOCKS_B, TPB>>>(out, (unsigned)(i * WORDS_B));
    }
}